// round 5
// baseline (speedup 1.0000x reference)
#include <cuda_runtime.h>
#include <cstdint>
#include <cstddef>

#define BB 32
#define NN 2048
#define DD 128
#define HH 128

// Scratch for q/k/v activations (allocation-free rule: static device arrays).
__device__ float g_q[BB * NN * HH];
__device__ float g_k[BB * NN * HH];
__device__ float g_v[BB * NN * HH];

// ---------- packed f32x2 helpers (projection kernel) ----------
__device__ __forceinline__ unsigned long long pk2(float lo, float hi) {
    unsigned long long r;
    asm("mov.b64 %0, {%1, %2};" : "=l"(r) : "f"(lo), "f"(hi));
    return r;
}
__device__ __forceinline__ float2 upk2(unsigned long long p) {
    float2 f;
    asm("mov.b64 {%0, %1}, %2;" : "=f"(f.x), "=f"(f.y) : "l"(p));
    return f;
}
__device__ __forceinline__ unsigned long long f2fma(unsigned long long a,
                                                    unsigned long long b,
                                                    unsigned long long c) {
    unsigned long long d;
    asm("fma.rn.f32x2 %0, %1, %2, %3;" : "=l"(d) : "l"(a), "l"(b), "l"(c));
    return d;
}

__device__ __forceinline__ uint32_t tf32r(float x) {
    uint32_t r;
    asm("cvt.rna.tf32.f32 %0, %1;" : "=r"(r) : "f"(x));
    return r;
}

// warp mma: D(16x8) += A(16x8,row,tf32) * B(8x8,col,tf32), fp32 accum
__device__ __forceinline__ void mma16n8k8(float* c, const uint32_t* a,
                                          uint32_t b0, uint32_t b1) {
    asm volatile(
        "mma.sync.aligned.m16n8k8.row.col.f32.tf32.tf32.f32 "
        "{%0,%1,%2,%3}, {%4,%5,%6,%7}, {%8,%9}, {%0,%1,%2,%3};"
        : "+f"(c[0]), "+f"(c[1]), "+f"(c[2]), "+f"(c[3])
        : "r"(a[0]), "r"(a[1]), "r"(a[2]), "r"(a[3]), "r"(b0), "r"(b1));
}

__device__ __forceinline__ uint32_t smem_u32(const void* p) {
    uint32_t a;
    asm("{ .reg .u64 t; cvta.to.shared.u64 t, %1; cvt.u32.u64 %0, t; }"
        : "=r"(a) : "l"(p));
    return a;
}

#define CP_ASYNC16(dst, src)                                                \
    asm volatile("cp.async.cg.shared.global [%0], [%1], 16;" ::             \
                     "r"(dst), "l"(src) : "memory")
#define CP_COMMIT() asm volatile("cp.async.commit_group;" ::: "memory")
#define CP_WAIT0() asm volatile("cp.async.wait_group 0;" ::: "memory")

// ============================================================
// Kernel A: fused QKV projection, out = tanh(x @ W + b)  (FFMA2)
// Stores tf32-PRE-ROUNDED values. For q and k, the feature (h) dim is
// permuted within 8-groups: c -> (c&3)*2 + (c>>2)  (QK^T invariant; lets
// the attention kernel fetch mma fragments with LDS.64).
// ============================================================
__global__ __launch_bounds__(256, 1) void proj_kernel(
    const float* __restrict__ x,
    const float* __restrict__ Wq, const float* __restrict__ bq,
    const float* __restrict__ Wk, const float* __restrict__ bk,
    const float* __restrict__ Wv, const float* __restrict__ bv) {
    extern __shared__ float sm[];
    float* xs = sm;              // 64*128
    float* ws = sm + 64 * 128;   // 32*128

    const float* W;
    const float* bias;
    float* outp;
    bool permute;
    if (blockIdx.y == 0)      { W = Wq; bias = bq; outp = g_q; permute = true; }
    else if (blockIdx.y == 1) { W = Wk; bias = bk; outp = g_k; permute = true; }
    else                      { W = Wv; bias = bv; outp = g_v; permute = false; }

    const int tid = threadIdx.x;
    const int rowg = tid >> 4;
    const int colg = tid & 15;
    const int row0 = blockIdx.x * 64;

    {
        const float4* src = reinterpret_cast<const float4*>(x + (size_t)row0 * DD);
        float4* dst = reinterpret_cast<float4*>(xs);
#pragma unroll
        for (int t = 0; t < 8; t++) dst[tid + t * 256] = src[tid + t * 256];
    }

    unsigned long long acc[4][4];
#pragma unroll
    for (int r = 0; r < 4; r++)
#pragma unroll
        for (int c = 0; c < 4; c++) acc[r][c] = 0ull;

#pragma unroll 1
    for (int chunk = 0; chunk < 4; chunk++) {
        const int kk0 = chunk * 32;
        __syncthreads();
        {
            const float4* src = reinterpret_cast<const float4*>(W + (size_t)kk0 * HH);
            float4* dst = reinterpret_cast<float4*>(ws);
#pragma unroll
            for (int t = 0; t < 4; t++) dst[tid + t * 256] = src[tid + t * 256];
        }
        __syncthreads();

#pragma unroll 2
        for (int kkl = 0; kkl < 32; kkl++) {
            const int kk = kk0 + kkl;
            float xv[4];
#pragma unroll
            for (int r = 0; r < 4; r++) xv[r] = xs[(rowg * 4 + r) * DD + kk];
            float4 wa = *reinterpret_cast<const float4*>(ws + kkl * HH + colg * 4);
            float4 wb = *reinterpret_cast<const float4*>(ws + kkl * HH + 64 + colg * 4);
            unsigned long long wp[4];
            wp[0] = *reinterpret_cast<unsigned long long*>(&wa.x);
            wp[1] = *reinterpret_cast<unsigned long long*>(&wa.z);
            wp[2] = *reinterpret_cast<unsigned long long*>(&wb.x);
            wp[3] = *reinterpret_cast<unsigned long long*>(&wb.z);
#pragma unroll
            for (int r = 0; r < 4; r++) {
                unsigned long long xp = pk2(xv[r], xv[r]);
#pragma unroll
                for (int c = 0; c < 4; c++) acc[r][c] = f2fma(xp, wp[c], acc[r][c]);
            }
        }
    }

    float4 ba = *reinterpret_cast<const float4*>(bias + colg * 4);
    float4 bb = *reinterpret_cast<const float4*>(bias + 64 + colg * 4);
#pragma unroll
    for (int r = 0; r < 4; r++) {
        float2 a0 = upk2(acc[r][0]);
        float2 a1 = upk2(acc[r][1]);
        float2 a2 = upk2(acc[r][2]);
        float2 a3 = upk2(acc[r][3]);
        float vals[8];
        vals[0] = __uint_as_float(tf32r(tanhf(a0.x + ba.x)));
        vals[1] = __uint_as_float(tf32r(tanhf(a0.y + ba.y)));
        vals[2] = __uint_as_float(tf32r(tanhf(a1.x + ba.z)));
        vals[3] = __uint_as_float(tf32r(tanhf(a1.y + ba.w)));
        vals[4] = __uint_as_float(tf32r(tanhf(a2.x + bb.x)));
        vals[5] = __uint_as_float(tf32r(tanhf(a2.y + bb.y)));
        vals[6] = __uint_as_float(tf32r(tanhf(a3.x + bb.z)));
        vals[7] = __uint_as_float(tf32r(tanhf(a3.y + bb.w)));
        float* orow = outp + (size_t)(row0 + rowg * 4 + r) * HH;
        if (permute) {
#pragma unroll
            for (int i = 0; i < 8; i++) {
                const int c = (i < 4) ? (colg * 4 + i) : (64 + colg * 4 + i - 4);
                const int g = c >> 3, cc = c & 7;
                const int p = (g << 3) | (((cc & 3) << 1) | (cc >> 2));
                orow[p] = vals[i];
            }
        } else {
            float4 oa, ob;
            oa.x = vals[0]; oa.y = vals[1]; oa.z = vals[2]; oa.w = vals[3];
            ob.x = vals[4]; ob.y = vals[5]; ob.z = vals[6]; ob.w = vals[7];
            *reinterpret_cast<float4*>(orow + colg * 4) = oa;
            *reinterpret_cast<float4*>(orow + 64 + colg * 4) = ob;
        }
    }
}

// ============================================================
// Kernel B: tf32 mma.sync flash attention v3.
//  - nb-half split (8+8) to cut live registers (no spills)
//  - mask loads prefetched before each QK half
//  - q/k h-permuted in gmem -> LDS.64 fragment fetches
//  - P in registers via shfl conversion; cp.async double-step prefetch
// smem: Qs[128][132] | Ks[128][132] | Vs[128][136]  (u32 words)
// ============================================================
#define QLDW 132
#define VLDW 136
#define KS_OFF (128 * QLDW)
#define VS_OFF (2 * 128 * QLDW)
#define SMEM_ATT ((2 * 128 * QLDW + 128 * VLDW) * 4)

__global__ __launch_bounds__(256, 1) void attn_mma(
    const float* __restrict__ mask, float* __restrict__ out) {
    extern __shared__ uint32_t smw[];
    uint32_t* Qs = smw;
    uint32_t* Ks = smw + KS_OFF;
    uint32_t* Vs = smw + VS_OFF;
    const uint32_t smb = smem_u32(smw);

    const int tid = threadIdx.x;
    const int lane = tid & 31;
    const int w = tid >> 5;
    const int b = blockIdx.x >> 4;
    const int i0 = (blockIdx.x & 15) << 7;
    const int qp = lane >> 2;
    const int ql = lane & 3;
    const int r0 = w * 16 + qp;

    const float* qg = g_q + ((size_t)(b * NN) + i0) * HH;
    const float* kg = g_k + (size_t)(b * NN) * HH;
    const float* vg = g_v + (size_t)(b * NN) * HH;

    // ---- prologue: stage Q, K0, V0 via cp.async ----
#pragma unroll
    for (int t = 0; t < 16; t++) {
        const int idx = tid + t * 256;
        const int row = idx >> 5, c4 = idx & 31;
        CP_ASYNC16(smb + (uint32_t)(row * QLDW + c4 * 4) * 4, qg + idx * 4);
        CP_ASYNC16(smb + (uint32_t)(KS_OFF + row * QLDW + c4 * 4) * 4, kg + idx * 4);
        CP_ASYNC16(smb + (uint32_t)(VS_OFF + row * VLDW + c4 * 4) * 4, vg + idx * 4);
    }
    CP_COMMIT();

    float oa[16][4];
#pragma unroll
    for (int h = 0; h < 16; h++)
#pragma unroll
        for (int c = 0; c < 4; c++) oa[h][c] = 0.0f;
    float ls0 = 0.0f, ls1 = 0.0f;

    const float* mrow0 = mask + ((size_t)(b * NN) + i0 + r0) * NN;
    const float* mrow1 = mrow0 + (size_t)8 * NN;

    const int L0 = qp * 4 + (ql >> 1);
    const bool odd = (ql & 1);

#pragma unroll 1
    for (int jt = 0; jt < 16; jt++) {
        const int j0 = jt << 7;
        CP_WAIT0();
        __syncthreads();   // K/V tiles for jt in smem; prior PV done with Vs

        uint32_t pa[16][4];

#pragma unroll 1
        for (int half = 0; half < 2; half++) {
            const int nb0 = half * 8;
            // ---- prefetch mask for this half (latency hidden by QK) ----
            float2 mh0[8], mh1[8];
#pragma unroll
            for (int nb = 0; nb < 8; nb++) {
                const int jcol = j0 + (nb0 + nb) * 8 + 2 * ql;
                mh0[nb] = __ldg(reinterpret_cast<const float2*>(mrow0 + jcol));
                mh1[nb] = __ldg(reinterpret_cast<const float2*>(mrow1 + jcol));
            }

            // ---- S half = Q K^T : k outer, 8 independent nb chains ----
            float sf[8][4];
#pragma unroll
            for (int nb = 0; nb < 8; nb++)
#pragma unroll
                for (int c = 0; c < 4; c++) sf[nb][c] = 0.0f;

#pragma unroll 4
            for (int k = 0; k < 16; k++) {
                const uint32_t* qb = Qs + r0 * QLDW + k * 8 + 2 * ql;
                uint2 q0 = *reinterpret_cast<const uint2*>(qb);
                uint2 q1 = *reinterpret_cast<const uint2*>(qb + 8 * QLDW);
                uint32_t qa[4] = {q0.x, q1.x, q0.y, q1.y};
#pragma unroll
                for (int nb = 0; nb < 8; nb++) {
                    uint2 kb = *reinterpret_cast<const uint2*>(
                        Ks + ((nb0 + nb) * 8 + qp) * QLDW + k * 8 + 2 * ql);
                    mma16n8k8(sf[nb], qa, kb.x, kb.y);
                }
            }

            // ---- mask + exp + D->A fragment conversion ----
            float nls0 = 0.0f, nls1 = 0.0f;
#pragma unroll
            for (int nb = 0; nb < 8; nb++) {
                uint32_t u0 = (mh0[nb].x != 0.0f) ? tf32r(__expf(sf[nb][0] - 40.0f)) : 0u;
                uint32_t u1 = (mh0[nb].y != 0.0f) ? tf32r(__expf(sf[nb][1] - 40.0f)) : 0u;
                uint32_t u2 = (mh1[nb].x != 0.0f) ? tf32r(__expf(sf[nb][2] - 40.0f)) : 0u;
                uint32_t u3 = (mh1[nb].y != 0.0f) ? tf32r(__expf(sf[nb][3] - 40.0f)) : 0u;
                nls0 += __uint_as_float(u0) + __uint_as_float(u1);
                nls1 += __uint_as_float(u2) + __uint_as_float(u3);
                uint32_t t00 = __shfl_sync(0xffffffffu, u0, L0);
                uint32_t t01 = __shfl_sync(0xffffffffu, u1, L0);
                uint32_t t10 = __shfl_sync(0xffffffffu, u2, L0);
                uint32_t t11 = __shfl_sync(0xffffffffu, u3, L0);
                uint32_t t20 = __shfl_sync(0xffffffffu, u0, L0 + 2);
                uint32_t t21 = __shfl_sync(0xffffffffu, u1, L0 + 2);
                uint32_t t30 = __shfl_sync(0xffffffffu, u2, L0 + 2);
                uint32_t t31 = __shfl_sync(0xffffffffu, u3, L0 + 2);
                pa[nb0 + nb][0] = odd ? t01 : t00;
                pa[nb0 + nb][1] = odd ? t11 : t10;
                pa[nb0 + nb][2] = odd ? t21 : t20;
                pa[nb0 + nb][3] = odd ? t31 : t30;
            }
            nls0 += __shfl_xor_sync(0xffffffffu, nls0, 1);
            nls0 += __shfl_xor_sync(0xffffffffu, nls0, 2);
            nls1 += __shfl_xor_sync(0xffffffffu, nls1, 1);
            nls1 += __shfl_xor_sync(0xffffffffu, nls1, 2);
            ls0 += nls0;
            ls1 += nls1;
        }

        __syncthreads();   // all warps done reading Ks
        if (jt < 15) {
            const float* kn = kg + ((size_t)(j0 + 128)) * HH;
#pragma unroll
            for (int t = 0; t < 16; t++) {
                const int idx = tid + t * 256;
                const int row = idx >> 5, c4 = idx & 31;
                CP_ASYNC16(smb + (uint32_t)(KS_OFF + row * QLDW + c4 * 4) * 4,
                           kn + idx * 4);
            }
            CP_COMMIT();
        }

        // ---- O += P V : h inner, 16 independent chains ----
#pragma unroll 4
        for (int k = 0; k < 16; k++) {
            const uint32_t* vb = Vs + (k * 8 + ql) * VLDW + qp;
#pragma unroll
            for (int h = 0; h < 16; h++) {
                mma16n8k8(oa[h], pa[k], vb[h * 8], vb[h * 8 + 4 * VLDW]);
            }
        }
        __syncthreads();   // all warps done reading Vs
        if (jt < 15) {
            const float* vn = vg + ((size_t)(j0 + 128)) * HH;
#pragma unroll
            for (int t = 0; t < 16; t++) {
                const int idx = tid + t * 256;
                const int row = idx >> 5, c4 = idx & 31;
                CP_ASYNC16(smb + (uint32_t)(VS_OFF + row * VLDW + c4 * 4) * 4,
                           vn + idx * 4);
            }
            CP_COMMIT();
        }
    }

    // ---- epilogue: normalize, store ----
    const float inv0 = 1.0f / ls0;
    const float inv1 = 1.0f / ls1;
    float* orow0 = out + ((size_t)(b * NN) + i0 + r0) * HH + 2 * ql;
    float* orow1 = orow0 + (size_t)8 * HH;
#pragma unroll
    for (int h = 0; h < 16; h++) {
        float2 v0, v1;
        v0.x = oa[h][0] * inv0; v0.y = oa[h][1] * inv0;
        v1.x = oa[h][2] * inv1; v1.y = oa[h][3] * inv1;
        *reinterpret_cast<float2*>(orow0 + h * 8) = v0;
        *reinterpret_cast<float2*>(orow1 + h * 8) = v1;
    }
}

extern "C" void kernel_launch(void* const* d_in, const int* in_sizes, int n_in,
                              void* d_out, int out_size) {
    const float* x    = (const float*)d_in[0];
    const float* mask = (const float*)d_in[1];
    const float* Wv   = (const float*)d_in[2];
    const float* bv   = (const float*)d_in[3];
    const float* Wk   = (const float*)d_in[4];
    const float* bk   = (const float*)d_in[5];
    const float* Wq   = (const float*)d_in[6];
    const float* bq   = (const float*)d_in[7];
    float* out = (float*)d_out;

    cudaFuncSetAttribute(proj_kernel, cudaFuncAttributeMaxDynamicSharedMemorySize,
                         49152);
    cudaFuncSetAttribute(attn_mma, cudaFuncAttributeMaxDynamicSharedMemorySize,
                         SMEM_ATT);

    proj_kernel<<<dim3(1024, 3, 1), 256, 49152>>>(x, Wq, bq, Wk, bk, Wv, bv);
    attn_mma<<<512, 256, SMEM_ATT>>>(mask, out);
}